// round 2
// baseline (speedup 1.0000x reference)
#include <cuda_runtime.h>

#define BDIM 32768
#define LDIM 7
#define TDIM 6
#define EDIM 256
#define HDIM 256
#define TB   32
#define NTHR 256

// ---- device scratch (static globals; no runtime allocation) ----
__device__ float g_Wg[HDIM * 1024];              // [h][q*256+e] = (W_edge @ W_{sel}) quadrant cat
__device__ float g_We[HDIM * 1024];              // [h][q*256+e] = W_{sel} quadrant cat (for edge_4)
__device__ float g_qt[(size_t)BDIM * HDIM];      // qt per row
__device__ float g_att[BDIM * LDIM];             // 10*tanh(masked att)
__device__ float g_cmax[LDIM];
__device__ float g_csum[LDIM];
__device__ int   g_is64;

// ---------------------------------------------------------------------------
// Sniff whether xes is int64 (little-endian: odd int32 words all zero) or int32
// ---------------------------------------------------------------------------
__global__ void k_sniff(const int* __restrict__ xes32) {
    if (threadIdx.x == 0 && blockIdx.x == 0) {
        int ok = 1;
        for (int i = 0; i < 32; ++i)
            if (xes32[2 * i + 1] != 0) ok = 0;
        g_is64 = ok;
    }
}

// ---------------------------------------------------------------------------
// Precompute W_edge @ W_x (4 matrices) into quadrant-cat g_Wg, and copy raw
// weights into quadrant-cat g_We. Quadrants: 0:(cond,enc_h,W_h) 1:(cond,enc_v,W_v)
// 2:(!cond,enc_h,Ws_h) 3:(!cond,enc_v,Ws_v)
// ---------------------------------------------------------------------------
__global__ __launch_bounds__(256) void k_prep(
    const float* __restrict__ We,
    const float* __restrict__ Wh, const float* __restrict__ Wv,
    const float* __restrict__ Wsh, const float* __restrict__ Wsv)
{
    int q = blockIdx.x >> 8;
    int h = blockIdx.x & 255;
    const float* Wq = (q == 0) ? Wh : (q == 1) ? Wv : (q == 2) ? Wsh : Wsv;
    __shared__ float we[256];
    int e = threadIdx.x;
    we[e] = We[h * 256 + e];
    __syncthreads();
    float s = 0.f;
#pragma unroll 8
    for (int m = 0; m < 256; ++m) s += we[m] * Wq[m * 256 + e];
    g_Wg[h * 1024 + (q << 8) + e] = s;
    g_We[h * 1024 + (q << 8) + e] = Wq[h * 256 + e];
}

// ---------------------------------------------------------------------------
// Main fused kernel: 1 CTA = 32 batch rows, 256 threads.
// Thread (ty=tid/32, tx=tid%32) owns rows ty*4..+3, cols tx+32j (j<8).
// ---------------------------------------------------------------------------
__global__ __launch_bounds__(256) void k_main(
    const float* __restrict__ enc, const int* __restrict__ xes32,
    const int* __restrict__ mask,
    const float* __restrict__ W_in, const float* __restrict__ b_in,
    const float* __restrict__ W_ctx, const float* __restrict__ b_ctx,
    const float* __restrict__ V)
{
    __shared__ float As[TB][36];
    __shared__ float Ws[256][33];
    __shared__ int s_h[5][TB], s_v[5][TB], s_c[5][TB];

    const int tid = threadIdx.x;
    const int b0  = blockIdx.x * TB;
    const int tx  = tid & 31, ty = tid >> 5;
    const int r0  = ty * 4;
    const int lr  = tid >> 3;          // loader row 0..31
    const int lk  = (tid & 7) << 2;    // loader k offset 0,4..28
    const int is64 = g_is64;

    // load xes for steps 0..4 (step 5 is dead: its edge/g never reach qt)
    for (int i = tid; i < 5 * TB; i += NTHR) {
        int t = i / TB, r = i - t * TB;
        size_t base = ((size_t)(b0 + r) * TDIM + t) * 3;
        int h, v, tt;
        if (is64) { h = xes32[2*base]; v = xes32[2*(base+1)]; tt = xes32[2*(base+2)]; }
        else      { h = xes32[base];   v = xes32[base+1];     tt = xes32[base+2]; }
        s_h[t][r] = h; s_v[t][r] = v; s_c[t][r] = (tt == 0);
    }
    __syncthreads();

    float gmax[4][8];
    float acc[4][8];
#pragma unroll
    for (int i = 0; i < 4; ++i)
#pragma unroll
        for (int j = 0; j < 8; ++j) gmax[i][j] = 0.f;

    // phases 0..4: g_t = edge_t @ W_edge^T (combined weights); phase 5: edge_4
    for (int phase = 0; phase < 6; ++phase) {
        const int t = (phase < 5) ? phase : 4;
        const float* Wsrc = (phase < 5) ? g_Wg : g_We;
#pragma unroll
        for (int i = 0; i < 4; ++i)
#pragma unroll
            for (int j = 0; j < 8; ++j) acc[i][j] = 0.f;

        const int myh = s_h[t][lr], myv = s_v[t][lr], myc = s_c[t][lr];

        for (int q = 0; q < 4; ++q) {
            const int idx  = (q & 1) ? myv : myh;
            const bool act = (q < 2) ? (myc != 0) : (myc == 0);
            const float* arow = enc + ((size_t)(b0 + lr) * LDIM + idx) * EDIM;

            for (int e0 = 0; e0 < EDIM; e0 += 32) {
                __syncthreads();
                float4 av = make_float4(0.f, 0.f, 0.f, 0.f);
                if (act) av = *reinterpret_cast<const float4*>(arow + e0 + lk);
                *reinterpret_cast<float4*>(&As[lr][lk]) = av;
#pragma unroll
                for (int i = 0; i < 8; ++i) {
                    int h = (tid >> 3) + (i << 5);
                    float4 wv = *reinterpret_cast<const float4*>(
                        &Wsrc[h * 1024 + (q << 8) + e0 + lk]);
                    Ws[h][lk]   = wv.x; Ws[h][lk+1] = wv.y;
                    Ws[h][lk+2] = wv.z; Ws[h][lk+3] = wv.w;
                }
                __syncthreads();
#pragma unroll
                for (int kk = 0; kk < 32; ++kk) {
                    float a0 = As[r0][kk], a1 = As[r0+1][kk];
                    float a2 = As[r0+2][kk], a3 = As[r0+3][kk];
#pragma unroll
                    for (int j = 0; j < 8; ++j) {
                        float w = Ws[tx + (j << 5)][kk];
                        acc[0][j] += a0 * w; acc[1][j] += a1 * w;
                        acc[2][j] += a2 * w; acc[3][j] += a3 * w;
                    }
                }
            }
        }
        if (phase < 5) {
#pragma unroll
            for (int i = 0; i < 4; ++i)
#pragma unroll
                for (int j = 0; j < 8; ++j) gmax[i][j] = fmaxf(gmax[i][j], acc[i][j]);
        } else {
            // qt = relu(edge_4 + max(0, g_0..g_4))  -> global scratch
#pragma unroll
            for (int i = 0; i < 4; ++i)
#pragma unroll
                for (int j = 0; j < 8; ++j) {
                    float qt = acc[i][j] + gmax[i][j];
                    qt = qt > 0.f ? qt : 0.f;
                    g_qt[(size_t)(b0 + r0 + i) * HDIM + tx + (j << 5)] = qt;
                }
        }
    }
    __syncthreads();  // g_qt visible block-wide

    // ---- inp = qt @ W_in^T + b_in ----
#pragma unroll
    for (int i = 0; i < 4; ++i)
#pragma unroll
        for (int j = 0; j < 8; ++j) acc[i][j] = 0.f;
    {
        const float* qrow = &g_qt[(size_t)(b0 + lr) * HDIM];
        for (int e0 = 0; e0 < HDIM; e0 += 32) {
            __syncthreads();
            float4 av = *reinterpret_cast<const float4*>(qrow + e0 + lk);
            *reinterpret_cast<float4*>(&As[lr][lk]) = av;
#pragma unroll
            for (int i = 0; i < 8; ++i) {
                int h = (tid >> 3) + (i << 5);
                float4 wv = *reinterpret_cast<const float4*>(&W_in[h * 256 + e0 + lk]);
                Ws[h][lk]   = wv.x; Ws[h][lk+1] = wv.y;
                Ws[h][lk+2] = wv.z; Ws[h][lk+3] = wv.w;
            }
            __syncthreads();
#pragma unroll
            for (int kk = 0; kk < 32; ++kk) {
                float a0 = As[r0][kk], a1 = As[r0+1][kk];
                float a2 = As[r0+2][kk], a3 = As[r0+3][kk];
#pragma unroll
                for (int j = 0; j < 8; ++j) {
                    float w = Ws[tx + (j << 5)][kk];
                    acc[0][j] += a0 * w; acc[1][j] += a1 * w;
                    acc[2][j] += a2 * w; acc[3][j] += a3 * w;
                }
            }
        }
    }
    float inp[4][8];
#pragma unroll
    for (int i = 0; i < 4; ++i)
#pragma unroll
        for (int j = 0; j < 8; ++j)
            inp[i][j] = acc[i][j] + __ldg(&b_in[tx + (j << 5)]);

    // ---- ctx per l; att = sum_h V[h]*tanh(inp+ctx); mask; 10*tanh ----
    for (int l = 0; l < LDIM; ++l) {
#pragma unroll
        for (int i = 0; i < 4; ++i)
#pragma unroll
            for (int j = 0; j < 8; ++j) acc[i][j] = 0.f;
        const float* erow = enc + ((size_t)(b0 + lr) * LDIM + l) * EDIM;
        for (int e0 = 0; e0 < EDIM; e0 += 32) {
            __syncthreads();
            float4 av = *reinterpret_cast<const float4*>(erow + e0 + lk);
            *reinterpret_cast<float4*>(&As[lr][lk]) = av;
#pragma unroll
            for (int i = 0; i < 8; ++i) {
                int h = (tid >> 3) + (i << 5);
                float4 wv = *reinterpret_cast<const float4*>(&W_ctx[h * 256 + e0 + lk]);
                Ws[h][lk]   = wv.x; Ws[h][lk+1] = wv.y;
                Ws[h][lk+2] = wv.z; Ws[h][lk+3] = wv.w;
            }
            __syncthreads();
#pragma unroll
            for (int kk = 0; kk < 32; ++kk) {
                float a0 = As[r0][kk], a1 = As[r0+1][kk];
                float a2 = As[r0+2][kk], a3 = As[r0+3][kk];
#pragma unroll
                for (int j = 0; j < 8; ++j) {
                    float w = Ws[tx + (j << 5)][kk];
                    acc[0][j] += a0 * w; acc[1][j] += a1 * w;
                    acc[2][j] += a2 * w; acc[3][j] += a3 * w;
                }
            }
        }
        float part[4] = {0.f, 0.f, 0.f, 0.f};
#pragma unroll
        for (int j = 0; j < 8; ++j) {
            int c = tx + (j << 5);
            float vv = __ldg(&V[c]);
            float bc = __ldg(&b_ctx[c]);
#pragma unroll
            for (int i = 0; i < 4; ++i)
                part[i] += vv * tanhf(inp[i][j] + acc[i][j] + bc);
        }
#pragma unroll
        for (int o = 16; o > 0; o >>= 1)
#pragma unroll
            for (int i = 0; i < 4; ++i)
                part[i] += __shfl_xor_sync(0xffffffffu, part[i], o);
        if (tx == 0) {
#pragma unroll
            for (int i = 0; i < 4; ++i) {
                int b = b0 + r0 + i;
                int m = mask[b * LDIM + l];
                float a = m ? part[i] : -1000000000.0f;
                g_att[b * LDIM + l] = 10.f * tanhf(a);
            }
        }
    }
}

// ---------------------------------------------------------------------------
// Column (axis=0) softmax stats: per l, max over batch and sum of exp(x-max)
// ---------------------------------------------------------------------------
__global__ void k_colred() {
    __shared__ float red[256];
    const int l = blockIdx.x, tid = threadIdx.x;
    float m = -3.4e38f;
    for (int b = tid; b < BDIM; b += 256) m = fmaxf(m, g_att[b * LDIM + l]);
    red[tid] = m; __syncthreads();
    for (int s = 128; s > 0; s >>= 1) {
        if (tid < s) red[tid] = fmaxf(red[tid], red[tid + s]);
        __syncthreads();
    }
    float bm = red[0];
    __syncthreads();
    float s = 0.f;
    for (int b = tid; b < BDIM; b += 256) s += expf(g_att[b * LDIM + l] - bm);
    red[tid] = s; __syncthreads();
    for (int st = 128; st > 0; st >>= 1) {
        if (tid < st) red[tid] += red[tid + st];
        __syncthreads();
    }
    if (tid == 0) { g_cmax[l] = bm; g_csum[l] = red[0]; }
}

// ---------------------------------------------------------------------------
// JAX threefry2x32, PARTITIONABLE path (jax_threefry_partitionable=True,
// the default in modern JAX): counter = uint64 iota -> (hi, lo) words,
// ctr pair = (0, i) for i < 2^32; 32-bit output = out0 ^ out1.
// key(42) -> (k1, k2) = (0, 42).
// ---------------------------------------------------------------------------
__device__ __forceinline__ unsigned rotl32(unsigned x, int r) {
    return (x << r) | (x >> (32 - r));
}
__device__ float gumbel_at(unsigned i) {
    const unsigned k0 = 0u, k1 = 42u, k2 = 0u ^ 42u ^ 0x1BD11BDAu;
    unsigned x0 = 0u + k0;     // counts_hi = 0 (i < 2^32)
    unsigned x1 = i + k1;      // counts_lo = i
#define TF_RG(a,b,c,d) \
    x0 += x1; x1 = rotl32(x1,(a)); x1 ^= x0; \
    x0 += x1; x1 = rotl32(x1,(b)); x1 ^= x0; \
    x0 += x1; x1 = rotl32(x1,(c)); x1 ^= x0; \
    x0 += x1; x1 = rotl32(x1,(d)); x1 ^= x0;
    TF_RG(13,15,26,6)   x0 += k1; x1 += k2 + 1u;
    TF_RG(17,29,16,24)  x0 += k2; x1 += k0 + 2u;
    TF_RG(13,15,26,6)   x0 += k0; x1 += k1 + 3u;
    TF_RG(17,29,16,24)  x0 += k1; x1 += k2 + 4u;
    TF_RG(13,15,26,6)   x0 += k2; x1 += k0 + 5u;
#undef TF_RG
    unsigned bits = x0 ^ x1;   // partitionable 32-bit harvest
    float f = __uint_as_float((bits >> 9) | 0x3f800000u) - 1.0f;
    const float tiny = 1.17549435e-38f;
    float u = fmaxf(tiny, f * (1.0f - tiny) + tiny);
    return -logf(-logf(u));
}

// ---------------------------------------------------------------------------
// Sampling + outputs: [idx (B), p (B), new_mask (B*7)] as float32
// ---------------------------------------------------------------------------
__global__ void k_sample(const int* __restrict__ mask, float* __restrict__ out) {
    int b = blockIdx.x * blockDim.x + threadIdx.x;
    if (b >= BDIM) return;
    float alpha[LDIM];
    float best = -3.4e38f;
    int bi = 0;
#pragma unroll
    for (int l = 0; l < LDIM; ++l) {
        float a10 = g_att[b * LDIM + l];
        float al = expf(a10 - g_cmax[l]) / g_csum[l];
        alpha[l] = al;
        float sc = logf(al) + gumbel_at((unsigned)(b * LDIM + l));
        if (sc > best) { best = sc; bi = l; }   // strict > keeps first max (jnp.argmax)
    }
    out[b] = (float)bi;
    out[BDIM + b] = alpha[bi];
#pragma unroll
    for (int l = 0; l < LDIM; ++l)
        out[2 * BDIM + b * LDIM + l] = (float)(mask[b * LDIM + l] - ((l == bi) ? 1 : 0));
}

// ---------------------------------------------------------------------------
extern "C" void kernel_launch(void* const* d_in, const int* in_sizes, int n_in,
                              void* d_out, int out_size) {
    const float* enc   = (const float*)d_in[0];
    const int*   xes32 = (const int*)d_in[1];   // int32 or int64 (sniffed)
    const int*   mask  = (const int*)d_in[2];
    const float* W_h   = (const float*)d_in[3];
    const float* W_v   = (const float*)d_in[4];
    const float* Ws_h  = (const float*)d_in[5];
    const float* Ws_v  = (const float*)d_in[6];
    const float* W_e   = (const float*)d_in[7];
    const float* W_in  = (const float*)d_in[8];
    const float* b_in  = (const float*)d_in[9];
    const float* W_ctx = (const float*)d_in[10];
    const float* b_ctx = (const float*)d_in[11];
    const float* V     = (const float*)d_in[12];
    float* out = (float*)d_out;

    k_sniff<<<1, 32>>>(xes32);
    k_prep<<<1024, 256>>>(W_e, W_h, W_v, Ws_h, Ws_v);
    k_main<<<BDIM / TB, NTHR>>>(enc, xes32, mask, W_in, b_in, W_ctx, b_ctx, V);
    k_colred<<<LDIM, 256>>>();
    k_sample<<<(BDIM + 255) / 256, 256>>>(mask, out);
    (void)in_sizes; (void)n_in; (void)out_size;
}

// round 3
// speedup vs baseline: 1.2548x; 1.2548x over previous
#include <cuda_runtime.h>

#define BDIM 32768
#define LDIM 7
#define TDIM 6
#define TB   64
#define NTHR 256
#define WSS  258   // Ws2 row stride (floats)
#define ASS  66    // As2 row stride (floats)

// ---- device scratch (static globals; no runtime allocation) ----
__device__ float g_Wg[256 * 1024];               // (W_edge @ W_sel) quadrant cat [h][q*256+e]
__device__ float g_We[256 * 1024];               // W_sel quadrant cat
__device__ float g_qt[(size_t)BDIM * 256];       // qt rows
__device__ float g_scr[(size_t)BDIM * 256];      // running g-max, then inp (thread-private RMW)
__device__ float g_att[BDIM * LDIM];             // 10*tanh(masked att)
__device__ float g_cmax[LDIM];
__device__ float g_csum[LDIM];
__device__ int   g_is64;

// ---- packed f32x2 helpers ----
__device__ __forceinline__ void ffma2(unsigned long long& d, unsigned long long a,
                                      unsigned long long b) {
    asm("fma.rn.f32x2 %0, %1, %2, %0;" : "+l"(d) : "l"(a), "l"(b));
}
__device__ __forceinline__ unsigned long long packdup(float x) {
    unsigned long long r;
    asm("mov.b64 %0, {%1, %1};" : "=l"(r) : "r"(__float_as_uint(x)));
    return r;
}
__device__ __forceinline__ float2 unpk(unsigned long long v) {
    float2 f;
    asm("mov.b64 {%0, %1}, %2;" : "=f"(f.x), "=f"(f.y) : "l"(v));
    return f;
}

// ---------------------------------------------------------------------------
// Sniff xes dtype (int64 little-endian has zero odd words)
// ---------------------------------------------------------------------------
__global__ void k_sniff(const int* __restrict__ xes32) {
    if (threadIdx.x == 0 && blockIdx.x == 0) {
        int ok = 1;
        for (int i = 0; i < 32; ++i)
            if (xes32[2 * i + 1] != 0) ok = 0;
        g_is64 = ok;
    }
}

// ---------------------------------------------------------------------------
// Precompute W_edge @ W_x into g_Wg, copy raw weights into g_We (quadrant cat)
// ---------------------------------------------------------------------------
__global__ __launch_bounds__(256) void k_prep(
    const float* __restrict__ We,
    const float* __restrict__ Wh, const float* __restrict__ Wv,
    const float* __restrict__ Wsh, const float* __restrict__ Wsv)
{
    int q = blockIdx.x >> 8;
    int h = blockIdx.x & 255;
    const float* Wq = (q == 0) ? Wh : (q == 1) ? Wv : (q == 2) ? Wsh : Wsv;
    __shared__ float we[256];
    int e = threadIdx.x;
    we[e] = We[h * 256 + e];
    __syncthreads();
    float s = 0.f;
#pragma unroll 8
    for (int m = 0; m < 256; ++m) s += we[m] * Wq[m * 256 + e];
    g_Wg[h * 1024 + (q << 8) + e] = s;
    g_We[h * 1024 + (q << 8) + e] = Wq[h * 256 + e];
}

// ---------------------------------------------------------------------------
// Tile loaders + packed FFMA2 compute core
// ---------------------------------------------------------------------------
__device__ __forceinline__ void load_w_tile(float* Ws2, const float* wbase, int rstride,
                                            int e0, int wlh, int wle) {
#pragma unroll
    for (int i = 0; i < 8; ++i) {
        int h = wlh + (i << 5);
        float4 wv = *reinterpret_cast<const float4*>(wbase + (size_t)h * rstride + e0 + wle);
        Ws2[(wle + 0) * WSS + h] = wv.x;
        Ws2[(wle + 1) * WSS + h] = wv.y;
        Ws2[(wle + 2) * WSS + h] = wv.z;
        Ws2[(wle + 3) * WSS + h] = wv.w;
    }
}
__device__ __forceinline__ void load_a_tile(float* As2, const float* arow, bool act,
                                            int e0, int alr, int ale) {
    float4 v1 = make_float4(0.f, 0.f, 0.f, 0.f), v2 = v1;
    if (act) {
        v1 = *reinterpret_cast<const float4*>(arow + e0 + ale);
        v2 = *reinterpret_cast<const float4*>(arow + e0 + ale + 4);
    }
    As2[(ale + 0) * ASS + alr] = v1.x; As2[(ale + 1) * ASS + alr] = v1.y;
    As2[(ale + 2) * ASS + alr] = v1.z; As2[(ale + 3) * ASS + alr] = v1.w;
    As2[(ale + 4) * ASS + alr] = v2.x; As2[(ale + 5) * ASS + alr] = v2.y;
    As2[(ale + 6) * ASS + alr] = v2.z; As2[(ale + 7) * ASS + alr] = v2.w;
}
__device__ __forceinline__ void compute_chunk(const float* Ws2, const float* As2,
                                              unsigned long long acc[8][4],
                                              int tx, int r0) {
#pragma unroll 8
    for (int kk = 0; kk < 32; ++kk) {
        const float* wrow = &Ws2[kk * WSS + 2 * tx];
        unsigned long long w0 = *reinterpret_cast<const unsigned long long*>(wrow);
        unsigned long long w1 = *reinterpret_cast<const unsigned long long*>(wrow + 64);
        unsigned long long w2 = *reinterpret_cast<const unsigned long long*>(wrow + 128);
        unsigned long long w3 = *reinterpret_cast<const unsigned long long*>(wrow + 192);
        const float* ar = &As2[kk * ASS + r0];
#pragma unroll
        for (int rr = 0; rr < 8; rr += 2) {
            float2 av = *reinterpret_cast<const float2*>(ar + rr);
            unsigned long long a0 = packdup(av.x);
            unsigned long long a1 = packdup(av.y);
            ffma2(acc[rr][0], a0, w0); ffma2(acc[rr][1], a0, w1);
            ffma2(acc[rr][2], a0, w2); ffma2(acc[rr][3], a0, w3);
            ffma2(acc[rr + 1][0], a1, w0); ffma2(acc[rr + 1][1], a1, w1);
            ffma2(acc[rr + 1][2], a1, w2); ffma2(acc[rr + 1][3], a1, w3);
        }
    }
}

// ---------------------------------------------------------------------------
// Main fused kernel: 1 CTA = 64 batch rows, 256 threads, 2 CTAs/SM.
// Warp wid owns rows r0=wid*8..+7; lane tx owns col pairs (2tx+64p, +1), p<4.
// ---------------------------------------------------------------------------
__global__ __launch_bounds__(NTHR, 2) void k_main(
    const float* __restrict__ enc, const int* __restrict__ xes32,
    const int* __restrict__ mask,
    const float* __restrict__ W_in, const float* __restrict__ b_in,
    const float* __restrict__ W_ctx, const float* __restrict__ b_ctx,
    const float* __restrict__ V)
{
    __shared__ __align__(16) float Ws2[32 * WSS];
    __shared__ __align__(16) float As2[32 * ASS];
    __shared__ int s_h[5][TB], s_v[5][TB], s_c[5][TB];

    const int tid = threadIdx.x;
    const int b0  = blockIdx.x * TB;
    const int tx  = tid & 31, wid = tid >> 5;
    const int r0  = wid << 3;
    const int wlh = tid >> 3;          // W-loader: h base (+32i)
    const int wle = (tid & 7) << 2;    // W-loader: e offset
    const int alr = tid >> 2;          // A-loader: row 0..63
    const int ale = (tid & 3) << 3;    // A-loader: e offset 0,8,16,24
    const int is64 = g_is64;

    // xes for steps 0..4 (step 5 is dead)
    for (int i = tid; i < 5 * TB; i += NTHR) {
        int t = i / TB, r = i - t * TB;
        size_t base = ((size_t)(b0 + r) * TDIM + t) * 3;
        int h, v, tt;
        if (is64) { h = xes32[2*base]; v = xes32[2*(base+1)]; tt = xes32[2*(base+2)]; }
        else      { h = xes32[base];   v = xes32[base+1];     tt = xes32[base+2]; }
        s_h[t][r] = h; s_v[t][r] = v; s_c[t][r] = (tt == 0);
    }
    __syncthreads();

    unsigned long long acc[8][4];
#pragma unroll
    for (int r = 0; r < 8; ++r)
#pragma unroll
        for (int p = 0; p < 4; ++p) acc[r][p] = 0ull;

    // ---- phases 0..4: g_t (combined weights); phase 5: edge_4 (raw) ----
    for (int phase = 0; phase < 6; ++phase) {
        const int t = (phase < 5) ? phase : 4;
        const float* Wsrc = (phase < 5) ? g_Wg : g_We;
        const int myh = s_h[t][alr], myv = s_v[t][alr], myc = s_c[t][alr];

        for (int q = 0; q < 4; ++q) {
            const int gidx = (q & 1) ? myv : myh;
            const bool act = (q < 2) ? (myc != 0) : (myc == 0);
            const float* arow = enc + ((size_t)(b0 + alr) * LDIM + gidx) * 256;
            const float* wbase = Wsrc + (q << 8);
            for (int e0 = 0; e0 < 256; e0 += 32) {
                __syncthreads();
                load_a_tile(As2, arow, act, e0, alr, ale);
                load_w_tile(Ws2, wbase, 1024, e0, wlh, wle);
                __syncthreads();
                compute_chunk(Ws2, As2, acc, tx, r0);
            }
        }
        // epilogue (thread-private (r,c) slice -> g_scr / g_qt; no sync needed)
        if (phase == 0) {
#pragma unroll
            for (int r = 0; r < 8; ++r)
#pragma unroll
                for (int p = 0; p < 4; ++p) {
                    float2 a = unpk(acc[r][p]);
                    *reinterpret_cast<float2*>(
                        &g_scr[(size_t)(b0 + r0 + r) * 256 + 2 * tx + 64 * p]) = a;
                }
        } else if (phase < 5) {
#pragma unroll
            for (int r = 0; r < 8; ++r)
#pragma unroll
                for (int p = 0; p < 4; ++p) {
                    float* sp = &g_scr[(size_t)(b0 + r0 + r) * 256 + 2 * tx + 64 * p];
                    float2 old = *reinterpret_cast<float2*>(sp);
                    float2 a = unpk(acc[r][p]);
                    old.x = fmaxf(old.x, a.x); old.y = fmaxf(old.y, a.y);
                    *reinterpret_cast<float2*>(sp) = old;
                }
        } else {
#pragma unroll
            for (int r = 0; r < 8; ++r)
#pragma unroll
                for (int p = 0; p < 4; ++p) {
                    const float* sp = &g_scr[(size_t)(b0 + r0 + r) * 256 + 2 * tx + 64 * p];
                    float2 gm = *reinterpret_cast<const float2*>(sp);
                    float2 e4 = unpk(acc[r][p]);
                    float qx = e4.x + fmaxf(gm.x, 0.f);
                    float qy = e4.y + fmaxf(gm.y, 0.f);
                    qx = qx > 0.f ? qx : 0.f;
                    qy = qy > 0.f ? qy : 0.f;
                    *reinterpret_cast<float2*>(
                        &g_qt[(size_t)(b0 + r0 + r) * 256 + 2 * tx + 64 * p]) =
                        make_float2(qx, qy);
                }
        }
#pragma unroll
        for (int r = 0; r < 8; ++r)
#pragma unroll
            for (int p = 0; p < 4; ++p) acc[r][p] = 0ull;
    }

    // ---- inp = qt @ W_in^T + b_in  (qt visible after first __syncthreads) ----
    {
        const float* arow = &g_qt[(size_t)(b0 + alr) * 256];
        for (int e0 = 0; e0 < 256; e0 += 32) {
            __syncthreads();
            load_a_tile(As2, arow, true, e0, alr, ale);
            load_w_tile(Ws2, W_in, 256, e0, wlh, wle);
            __syncthreads();
            compute_chunk(Ws2, As2, acc, tx, r0);
        }
#pragma unroll
        for (int r = 0; r < 8; ++r)
#pragma unroll
            for (int p = 0; p < 4; ++p) {
                int c0 = 2 * tx + 64 * p;
                float2 bi = *reinterpret_cast<const float2*>(&b_in[c0]);
                float2 a = unpk(acc[r][p]);
                *reinterpret_cast<float2*>(&g_scr[(size_t)(b0 + r0 + r) * 256 + c0]) =
                    make_float2(a.x + bi.x, a.y + bi.y);
                acc[r][p] = 0ull;
            }
    }

    // ---- ctx per l; att = sum_h V[h]*tanh(inp+ctx); mask; 10*tanh ----
    for (int l = 0; l < LDIM; ++l) {
        const float* arow = enc + ((size_t)(b0 + alr) * LDIM + l) * 256;
        for (int e0 = 0; e0 < 256; e0 += 32) {
            __syncthreads();
            load_a_tile(As2, arow, true, e0, alr, ale);
            load_w_tile(Ws2, W_ctx, 256, e0, wlh, wle);
            __syncthreads();
            compute_chunk(Ws2, As2, acc, tx, r0);
        }
        float part[8];
#pragma unroll
        for (int r = 0; r < 8; ++r) part[r] = 0.f;
#pragma unroll
        for (int p = 0; p < 4; ++p) {
            int c0 = 2 * tx + 64 * p;
            float2 vv = *reinterpret_cast<const float2*>(&V[c0]);
            float2 bc = *reinterpret_cast<const float2*>(&b_ctx[c0]);
#pragma unroll
            for (int r = 0; r < 8; ++r) {
                float2 ip = *reinterpret_cast<const float2*>(
                    &g_scr[(size_t)(b0 + r0 + r) * 256 + c0]);
                float2 a = unpk(acc[r][p]);
                part[r] += vv.x * tanhf(ip.x + a.x + bc.x);
                part[r] += vv.y * tanhf(ip.y + a.y + bc.y);
                acc[r][p] = 0ull;
            }
        }
#pragma unroll
        for (int o = 16; o > 0; o >>= 1)
#pragma unroll
            for (int r = 0; r < 8; ++r)
                part[r] += __shfl_xor_sync(0xffffffffu, part[r], o);
        if (tx == 0) {
#pragma unroll
            for (int r = 0; r < 8; ++r) {
                int b = b0 + r0 + r;
                int m = mask[b * LDIM + l];
                float a = m ? part[r] : -1000000000.0f;
                g_att[b * LDIM + l] = 10.f * tanhf(a);
            }
        }
    }
}

// ---------------------------------------------------------------------------
// Column (axis=0) softmax stats
// ---------------------------------------------------------------------------
__global__ void k_colred() {
    __shared__ float red[256];
    const int l = blockIdx.x, tid = threadIdx.x;
    float m = -3.4e38f;
    for (int b = tid; b < BDIM; b += 256) m = fmaxf(m, g_att[b * LDIM + l]);
    red[tid] = m; __syncthreads();
    for (int s = 128; s > 0; s >>= 1) {
        if (tid < s) red[tid] = fmaxf(red[tid], red[tid + s]);
        __syncthreads();
    }
    float bm = red[0];
    __syncthreads();
    float s = 0.f;
    for (int b = tid; b < BDIM; b += 256) s += expf(g_att[b * LDIM + l] - bm);
    red[tid] = s; __syncthreads();
    for (int st = 128; st > 0; st >>= 1) {
        if (tid < st) red[tid] += red[tid + st];
        __syncthreads();
    }
    if (tid == 0) { g_cmax[l] = bm; g_csum[l] = red[0]; }
}

// ---------------------------------------------------------------------------
// JAX threefry2x32, partitionable path: ctr=(0,i), out = x0 ^ x1
// ---------------------------------------------------------------------------
__device__ __forceinline__ unsigned rotl32(unsigned x, int r) {
    return (x << r) | (x >> (32 - r));
}
__device__ float gumbel_at(unsigned i) {
    const unsigned k0 = 0u, k1 = 42u, k2 = 0u ^ 42u ^ 0x1BD11BDAu;
    unsigned x0 = 0u + k0;
    unsigned x1 = i + k1;
#define TF_RG(a,b,c,d) \
    x0 += x1; x1 = rotl32(x1,(a)); x1 ^= x0; \
    x0 += x1; x1 = rotl32(x1,(b)); x1 ^= x0; \
    x0 += x1; x1 = rotl32(x1,(c)); x1 ^= x0; \
    x0 += x1; x1 = rotl32(x1,(d)); x1 ^= x0;
    TF_RG(13,15,26,6)   x0 += k1; x1 += k2 + 1u;
    TF_RG(17,29,16,24)  x0 += k2; x1 += k0 + 2u;
    TF_RG(13,15,26,6)   x0 += k0; x1 += k1 + 3u;
    TF_RG(17,29,16,24)  x0 += k1; x1 += k2 + 4u;
    TF_RG(13,15,26,6)   x0 += k2; x1 += k0 + 5u;
#undef TF_RG
    unsigned bits = x0 ^ x1;
    float f = __uint_as_float((bits >> 9) | 0x3f800000u) - 1.0f;
    const float tiny = 1.17549435e-38f;
    float u = fmaxf(tiny, f * (1.0f - tiny) + tiny);
    return -logf(-logf(u));
}

// ---------------------------------------------------------------------------
// Sampling + outputs: [idx (B), p (B), new_mask (B*7)] as float32
// ---------------------------------------------------------------------------
__global__ void k_sample(const int* __restrict__ mask, float* __restrict__ out) {
    int b = blockIdx.x * blockDim.x + threadIdx.x;
    if (b >= BDIM) return;
    float alpha[LDIM];
    float best = -3.4e38f;
    int bi = 0;
#pragma unroll
    for (int l = 0; l < LDIM; ++l) {
        float a10 = g_att[b * LDIM + l];
        float al = expf(a10 - g_cmax[l]) / g_csum[l];
        alpha[l] = al;
        float sc = logf(al) + gumbel_at((unsigned)(b * LDIM + l));
        if (sc > best) { best = sc; bi = l; }
    }
    out[b] = (float)bi;
    out[BDIM + b] = alpha[bi];
#pragma unroll
    for (int l = 0; l < LDIM; ++l)
        out[2 * BDIM + b * LDIM + l] = (float)(mask[b * LDIM + l] - ((l == bi) ? 1 : 0));
}

// ---------------------------------------------------------------------------
extern "C" void kernel_launch(void* const* d_in, const int* in_sizes, int n_in,
                              void* d_out, int out_size) {
    const float* enc   = (const float*)d_in[0];
    const int*   xes32 = (const int*)d_in[1];
    const int*   mask  = (const int*)d_in[2];
    const float* W_h   = (const float*)d_in[3];
    const float* W_v   = (const float*)d_in[4];
    const float* Ws_h  = (const float*)d_in[5];
    const float* Ws_v  = (const float*)d_in[6];
    const float* W_e   = (const float*)d_in[7];
    const float* W_in  = (const float*)d_in[8];
    const float* b_in  = (const float*)d_in[9];
    const float* W_ctx = (const float*)d_in[10];
    const float* b_ctx = (const float*)d_in[11];
    const float* V     = (const float*)d_in[12];
    float* out = (float*)d_out;

    k_sniff<<<1, 32>>>(xes32);
    k_prep<<<1024, 256>>>(W_e, W_h, W_v, Ws_h, Ws_v);
    k_main<<<BDIM / TB, NTHR>>>(enc, xes32, mask, W_in, b_in, W_ctx, b_ctx, V);
    k_colred<<<LDIM, 256>>>();
    k_sample<<<(BDIM + 255) / 256, 256>>>(mask, out);
    (void)in_sizes; (void)n_in; (void)out_size;
}